// round 12
// baseline (speedup 1.0000x reference)
#include <cuda_runtime.h>
#include <cuda_bf16.h>
#include <cuda_fp16.h>
#include <math.h>
#include <stdint.h>

#define B 4
#define C 64
#define CQK 128
#define HDIM 256
#define WDIM 256
#define HW 65536
#define HEADS 8

// ---------------- scratch ----------------------------------------------------
__device__ __nv_bfloat16 g_qk_pre[(size_t)B * CQK * HW];   // bf16 planar q/k
__device__ uint32_t g_y2[(size_t)B * 32 * HW];             // fp16 ch-pair interleaved
__device__ float g_sumsq[B * CQK];
__device__ float g_gram[B * HEADS * 8 * 8];
__device__ uint32_t g_Wt2[25 * 64 * 32];                   // m2 w: [tap][oc][ic2] f16x2
__device__ uint32_t g_Wpw[32 * 200];                       // qkv+m1 w: [ic2][oc] f16x2

// ---------------- helpers -----------------------------------------------------
__device__ __forceinline__ void mma_f16(float* d, const uint32_t* a, const uint32_t* b) {
    asm volatile(
        "mma.sync.aligned.m16n8k16.row.col.f32.f16.f16.f32 "
        "{%0,%1,%2,%3}, {%4,%5,%6,%7}, {%8,%9}, {%0,%1,%2,%3};"
        : "+f"(d[0]), "+f"(d[1]), "+f"(d[2]), "+f"(d[3])
        : "r"(a[0]), "r"(a[1]), "r"(a[2]), "r"(a[3]), "r"(b[0]), "r"(b[1]));
}

__device__ __forceinline__ void ldsm_x4(uint32_t* r, uint32_t saddr) {
    asm volatile("ldmatrix.sync.aligned.m8n8.x4.shared.b16 {%0,%1,%2,%3}, [%4];"
                 : "=r"(r[0]), "=r"(r[1]), "=r"(r[2]), "=r"(r[3]) : "r"(saddr));
}

__device__ __forceinline__ void cp_async16(uint32_t daddr, const void* src) {
    asm volatile("cp.async.cg.shared.global [%0], [%1], 16;" :: "r"(daddr), "l"(src));
}

__device__ __forceinline__ void cp_async8(uint32_t daddr, const void* src) {
    asm volatile("cp.async.ca.shared.global [%0], [%1], 8;" :: "r"(daddr), "l"(src));
}

__device__ __forceinline__ void cp_async4_zfill(uint32_t daddr, const void* src, int sz) {
    asm volatile("cp.async.ca.shared.global [%0], [%1], 4, %2;"
                 :: "r"(daddr), "l"(src), "r"(sz));
}

__device__ __forceinline__ float2 bf2f(uint32_t u) {
    float2 r;
    r.x = __uint_as_float(u << 16);
    r.y = __uint_as_float(u & 0xFFFF0000u);
    return r;
}

__device__ __forceinline__ uint32_t packh2(float lo, float hi) {
    __half2 p = __floats2half2_rn(lo, hi);
    return *(uint32_t*)&p;
}

// ---------------- K_prep_pw: pack pointwise weights only ----------------------
__global__ void k_prep_pw(const float* __restrict__ w_qkv,
                          const float* __restrict__ w_m1) {
    int j = blockIdx.x * 256 + threadIdx.x;
    if (j < 6400) {
        int ic2 = j / 200, oc = j - (j / 200) * 200;
        float w0 = 0.0f, w1 = 0.0f;
        if (oc < 128) {
            w0 = w_qkv[oc * 64 + 2 * ic2];
            w1 = w_qkv[oc * 64 + 2 * ic2 + 1];
        } else if (oc < 192) {
            w0 = w_m1[(oc - 128) * 64 + 2 * ic2];
            w1 = w_m1[(oc - 128) * 64 + 2 * ic2 + 1];
        }
        g_Wpw[j] = packh2(w0, w1);
    }
}

// ---------------- K0: fp16-MMA fused 1x1 convs (+ m2 packing + zero) ----------
#define XST2 136
#define WST2 200

__global__ __launch_bounds__(256, 2)
void k_pointwise(const float* __restrict__ x,
                 const float* __restrict__ b_qkv,
                 const float* __restrict__ bn_g,
                 const float* __restrict__ bn_b,
                 const float* __restrict__ bn_m,
                 const float* __restrict__ bn_v,
                 const float* __restrict__ w_m2) {
    extern __shared__ uint32_t smu[];
    uint32_t* xs2 = smu;
    uint32_t* ws2 = smu + 32 * XST2;
    float* sscale = (float*)(smu + 32 * XST2 + 32 * WST2);
    float* sshift = sscale + 192;

    const int tid = threadIdx.x;
    const int b = blockIdx.y;
    const int p0 = blockIdx.x * 128;

    {
        uint32_t base = (uint32_t)__cvta_generic_to_shared(ws2);
        for (int i = tid * 4; i < 6400; i += 1024)
            cp_async16(base + (uint32_t)i * 4u, g_Wpw + i);
        asm volatile("cp.async.commit_group;");
    }

    // ---- side work: pack m2 weights transposed [t][oc][ic2], zero buffers ----
    {
        int gbid = blockIdx.y * gridDim.x + blockIdx.x;
        if (gbid < 200) {
            int i = gbid * 256 + tid;        // < 51200
            int t = i / 2048;
            int rem = i & 2047;
            int oc = rem >> 5, ic2 = rem & 31;
            float w0 = w_m2[(oc * 64 + 2 * ic2) * 25 + t];
            float w1 = w_m2[(oc * 64 + 2 * ic2 + 1) * 25 + t];
            g_Wt2[i] = packh2(w0, w1);
        } else if (gbid < 210) {
            int i = (gbid - 200) * 256 + tid;
            if (i < B * CQK) g_sumsq[i] = 0.0f;
            if (i < B * HEADS * 64) g_gram[i] = 0.0f;
        }
    }

    for (int i = tid; i < 192; i += 256) {
        if (i < 128) { sscale[i] = 1.0f; sshift[i] = b_qkv[i]; }
        else {
            int cc = i - 128;
            float s = bn_g[cc] * rsqrtf(bn_v[cc] + 1e-5f);
            sscale[i] = s;
            sshift[i] = bn_b[cc] - bn_m[cc] * s;
        }
    }
    for (int i = tid * 4; i < 32 * 128; i += 1024) {
        int ic2 = i >> 7, px = i & 127;
        float4 xa = *(const float4*)(x + (size_t)(b * 64 + 2 * ic2) * HW + p0 + px);
        float4 xb = *(const float4*)(x + (size_t)(b * 64 + 2 * ic2 + 1) * HW + p0 + px);
        uint4 u;
        u.x = packh2(xa.x, xb.x);
        u.y = packh2(xa.y, xb.y);
        u.z = packh2(xa.z, xb.z);
        u.w = packh2(xa.w, xb.w);
        *(uint4*)(xs2 + ic2 * XST2 + px) = u;
    }
    asm volatile("cp.async.wait_group 0;");
    __syncthreads();

    const int w = tid >> 5, lane = tid & 31;
    const int g = lane >> 2, t4 = lane & 3;
    const int mg = w >> 1, ng = w & 1;
    const int ocb = mg * 48;
    const int pxb = ng * 64;

    float acc[3][8][4];
#pragma unroll
    for (int mt = 0; mt < 3; mt++)
#pragma unroll
        for (int nf = 0; nf < 8; nf++)
#pragma unroll
            for (int j = 0; j < 4; j++) acc[mt][nf][j] = 0.0f;

#pragma unroll
    for (int ks = 0; ks < 4; ks++) {
        int ic2a = ks * 8 + t4;
        uint32_t a[3][4], bf[8][2];
#pragma unroll
        for (int mt = 0; mt < 3; mt++) {
            int ab = ic2a * WST2 + ocb + mt * 16 + g;
            a[mt][0] = ws2[ab];
            a[mt][1] = ws2[ab + 8];
            a[mt][2] = ws2[ab + 4 * WST2];
            a[mt][3] = ws2[ab + 4 * WST2 + 8];
        }
#pragma unroll
        for (int nf = 0; nf < 8; nf++) {
            int bb = ic2a * XST2 + pxb + nf * 8 + g;
            bf[nf][0] = xs2[bb];
            bf[nf][1] = xs2[bb + 4 * XST2];
        }
#pragma unroll
        for (int mt = 0; mt < 3; mt++)
#pragma unroll
            for (int nf = 0; nf < 8; nf++)
                mma_f16(acc[mt][nf], a[mt], bf[nf]);
    }

#pragma unroll
    for (int mt = 0; mt < 3; mt++) {
#pragma unroll
        for (int half = 0; half < 2; half++) {
            int oc = ocb + mt * 16 + half * 8 + g;
            float sc = sscale[oc], sh = sshift[oc];
            bool is_y = (oc >= 128);
#pragma unroll
            for (int nf = 0; nf < 8; nf++) {
                float v0 = acc[mt][nf][half * 2 + 0] * sc + sh;
                float v1 = acc[mt][nf][half * 2 + 1] * sc + sh;
                int px = p0 + pxb + nf * 8 + 2 * t4;
                if (!is_y) {
                    __nv_bfloat162 p = __floats2bfloat162_rn(v0, v1);
                    *(uint32_t*)&g_qk_pre[(size_t)(b * 128 + oc) * HW + px] =
                        *(uint32_t*)&p;
                } else {
                    float o0 = __shfl_down_sync(0xffffffffu, v0, 4);
                    float o1 = __shfl_down_sync(0xffffffffu, v1, 4);
                    if ((g & 1) == 0) {
                        int c2 = (oc - 128) >> 1;
                        uint2 u;
                        u.x = packh2(v0, o0);
                        u.y = packh2(v1, o1);
                        *(uint2*)&g_y2[(size_t)(b * 32 + c2) * HW + px] = u;
                    }
                }
            }
        }
    }
}

// ---------------- K1: fused depthwise3x3 + gram + sumsq (unchanged R11) -------
#define SR_U 18
#define CH_U 616
#define DV_OFF (16 * CH_U)
#define DV_CH 516
#define WSM_U (DV_OFF + 16 * DV_CH)
#define BSM_U (WSM_U + 144)
#define TOT_U (BSM_U + 16)

__global__ __launch_bounds__(256, 3)
void k_dwgram(const float* __restrict__ w_dw,
              const float* __restrict__ b_dw) {
    extern __shared__ uint32_t smu[];
    float* wsm = (float*)(smu + WSM_U);
    float* bsm = (float*)(smu + BSM_U);

    const int bh = blockIdx.z;
    const int b = bh >> 3, h = bh & 7;
    const int tx0 = blockIdx.x * 32, ty0 = blockIdx.y * 32;
    const int tid = threadIdx.x;
    const int w = tid >> 5, lane = tid & 31;
    const uint32_t smbase = (uint32_t)__cvta_generic_to_shared(smu);

    const __nv_bfloat16* gbase = g_qk_pre + (size_t)b * CQK * HW;
#pragma unroll
    for (int k = 0; k < 39; k++) {
        int idx = tid + k * 256;
        if (idx < 16 * 34 * SR_U) {
            int c16 = idx / (34 * SR_U);
            int rem = idx - c16 * (34 * SR_U);
            int r = rem / SR_U, cc = rem - r * SR_U;
            int ch = (c16 < 8) ? h * 8 + c16 : 64 + h * 8 + (c16 - 8);
            int gy = ty0 - 1 + r;
            int gx = tx0 - 2 + 2 * cc;
            bool ok = (gy >= 0) && (gy < HDIM) && (gx >= 0) && (gx < WDIM);
            const void* src = ok ? (const void*)(gbase + (size_t)ch * HW + gy * WDIM + gx)
                                 : (const void*)gbase;
            cp_async4_zfill(smbase + (uint32_t)(c16 * CH_U + r * SR_U + cc) * 4u,
                            src, ok ? 4 : 0);
        }
    }
    asm volatile("cp.async.commit_group;");

    for (int i = tid; i < 144; i += 256) {
        int c16 = i / 9, t = i - c16 * 9;
        int ch = (c16 < 8) ? h * 8 + c16 : 64 + h * 8 + (c16 - 8);
        wsm[i] = w_dw[ch * 9 + t];
    }
    if (tid < 16) {
        int ch = (tid < 8) ? h * 8 + tid : 64 + h * 8 + (tid - 8);
        bsm[tid] = b_dw[ch];
    }
    asm volatile("cp.async.wait_group 0;");
    __syncthreads();

    const int q = tid & 7, py = tid >> 3;
    float ssq[16];
#pragma unroll
    for (int i = 0; i < 16; i++) ssq[i] = 0.0f;

#pragma unroll
    for (int c16 = 0; c16 < 16; c16++) {
        float f[3][8];
#pragma unroll
        for (int dy = 0; dy < 3; dy++) {
            const uint2* p2 = (const uint2*)(smu + c16 * CH_U + (py + dy) * SR_U + 2 * q);
            uint2 u01 = p2[0], u23 = p2[1];
            float2 a0 = bf2f(u01.x), a1 = bf2f(u01.y);
            float2 a2 = bf2f(u23.x), a3 = bf2f(u23.y);
            f[dy][0] = a0.x; f[dy][1] = a0.y; f[dy][2] = a1.x; f[dy][3] = a1.y;
            f[dy][4] = a2.x; f[dy][5] = a2.y; f[dy][6] = a3.x; f[dy][7] = a3.y;
        }
        float bias = bsm[c16];
        float o[4];
#pragma unroll
        for (int xx = 0; xx < 4; xx++) {
            float a = bias;
#pragma unroll
            for (int dy = 0; dy < 3; dy++) {
                a = fmaf(wsm[c16 * 9 + dy * 3 + 0], f[dy][xx + 1], a);
                a = fmaf(wsm[c16 * 9 + dy * 3 + 1], f[dy][xx + 2], a);
                a = fmaf(wsm[c16 * 9 + dy * 3 + 2], f[dy][xx + 3], a);
            }
            o[xx] = a;
            ssq[c16] = fmaf(a, a, ssq[c16]);
        }
        uint2 dvu;
        __nv_bfloat162 p0 = __floats2bfloat162_rn(o[0], o[1]);
        __nv_bfloat162 p1 = __floats2bfloat162_rn(o[2], o[3]);
        dvu.x = *(uint32_t*)&p0;
        dvu.y = *(uint32_t*)&p1;
        *(uint2*)(smu + DV_OFF + c16 * DV_CH + py * 16 + 2 * q) = dvu;
    }
    __syncthreads();

    float gacc[8];
#pragma unroll
    for (int j = 0; j < 8; j++) gacc[j] = 0.0f;

    const uint32_t* dvq = smu + DV_OFF + w * DV_CH;
    const uint32_t* dvk = smu + DV_OFF + 8 * DV_CH;
#pragma unroll
    for (int s = 0; s < 8; s++) {
        int ui = s * 64 + lane * 2;
        uint2 uq = *(const uint2*)(dvq + ui);
        float2 q01 = bf2f(uq.x), q23 = bf2f(uq.y);
#pragma unroll
        for (int j = 0; j < 8; j++) {
            uint2 uk = *(const uint2*)(dvk + j * DV_CH + ui);
            float2 k01 = bf2f(uk.x), k23 = bf2f(uk.y);
            float s2 = gacc[j];
            s2 = fmaf(q01.x, k01.x, s2);
            s2 = fmaf(q01.y, k01.y, s2);
            s2 = fmaf(q23.x, k23.x, s2);
            s2 = fmaf(q23.y, k23.y, s2);
            gacc[j] = s2;
        }
    }

#pragma unroll
    for (int j = 0; j < 8; j++) {
        float s = gacc[j];
#pragma unroll
        for (int off = 16; off; off >>= 1) s += __shfl_xor_sync(0xffffffffu, s, off);
        if (lane == 0) atomicAdd(&g_gram[bh * 64 + w * 8 + j], s);
    }
    float* red = (float*)smu;
#pragma unroll
    for (int cidx = 0; cidx < 16; cidx++) {
        float s = ssq[cidx];
#pragma unroll
        for (int off = 16; off; off >>= 1) s += __shfl_xor_sync(0xffffffffu, s, off);
        if (lane == 0) red[w * 16 + cidx] = s;
    }
    __syncthreads();
    if (tid < 16) {
        float s = 0.0f;
#pragma unroll
        for (int w2 = 0; w2 < 8; w2++) s += red[w2 * 16 + tid];
        int ch = (tid < 8) ? h * 8 + tid : 64 + h * 8 + (tid - 8);
        atomicAdd(&g_sumsq[b * CQK + ch], s);
    }
}

// ---------------- K3: fp16 conv5x5 (ldmatrix-B) + gate + fp16 epilogue --------
#define YS2 408
#define WTR 36                              // transposed weight row stride (uints)
#define WS2 72                              // epilogue M stride
#define VST2 264
#define RING_OFF (32 * YS2)                 // 13056
#define TAP_U (64 * WTR)                    // 2304
#define PAIR_U (2 * TAP_U)                  // 4608
#define ATTN_OFF (RING_OFF + 3 * PAIR_U)    // 26880
#define K3_TOT (ATTN_OFF + 512)             // 27392 uints

__global__ __launch_bounds__(256, 2)
void k_conv5_out(const float* __restrict__ x,
                 const float* __restrict__ w_proj,
                 const float* __restrict__ temperature,
                 const float* __restrict__ b_proj,
                 float* __restrict__ out) {
    extern __shared__ uint32_t smu[];
    uint32_t* ysm2 = smu;
    uint32_t* ring = smu + RING_OFF;
    float* attn_s  = (float*)(smu + ATTN_OFF);

    const int b = blockIdx.z;
    const int tx0 = blockIdx.x * 16, ty0 = blockIdx.y * 16;
    const int tid = threadIdx.x;
    const int w = tid >> 5, lane = tid & 31;
    const int g = lane >> 2, t4 = lane & 3;
    const uint32_t smbase = (uint32_t)__cvta_generic_to_shared(smu);

    // ldmatrix lane constants: oc row select + k-offset select
    const int rowsel = (lane & 7) + 8 * ((lane >> 4) & 1);
    const int ksel = 4 * ((lane >> 3) & 1);
    const uint32_t ldsm_lane_off = (uint32_t)(rowsel * WTR + ksel) * 4u;
    const uint32_t ring_base = smbase + (uint32_t)RING_OFF * 4u;

    // ---- stage y tile + pair-0 weights (one commit group) --------------------
    const bool interior = (blockIdx.x >= 1) && (blockIdx.x <= 14) &&
                          (blockIdx.y >= 1) && (blockIdx.y <= 14);
    if (interior) {
        const uint32_t* yb = g_y2 + (size_t)(b * 32) * HW + (ty0 - 2) * WDIM + (tx0 - 2);
#pragma unroll
        for (int k = 0; k < 25; k++) {
            int i = tid + k * 256;
            int ic2 = i / 200;
            int rem = i - ic2 * 200;
            int r = rem / 10, cc = rem - r * 10;
            cp_async8(smbase + (uint32_t)((ic2 * YS2 + r * 20 + cc * 2) * 4),
                      yb + (size_t)ic2 * HW + r * WDIM + cc * 2);
        }
    } else {
        for (int i = tid; i < 32 * 400; i += 256) {
            int ic2 = i / 400;
            int rem = i - ic2 * 400;
            int r = rem / 20, cc = rem - r * 20;
            int gy = ty0 - 2 + r, gx = tx0 - 2 + cc;
            uint32_t v = 0;
            if (gy >= 0 && gy < HDIM && gx >= 0 && gx < WDIM)
                v = g_y2[(size_t)(b * 32 + ic2) * HW + gy * WDIM + gx];
            ysm2[ic2 * YS2 + r * 20 + cc] = v;
        }
    }
    // FILL_TAP: copy tap (64 rows x 32 uints) into padded rows of WTR=36
#define FILL_TAP(slot_u, tap)                                                  \
    do {                                                                       \
        const uint32_t* _src = g_Wt2 + (tap) * 2048;                           \
        uint32_t _db = smbase + (uint32_t)((RING_OFF + (slot_u)) * 4);         \
        for (int _i = tid * 4; _i < 2048; _i += 1024) {                        \
            int _oc = _i >> 5, _ic2 = _i & 31;                                 \
            cp_async16(_db + (uint32_t)(_oc * WTR + _ic2) * 4u, _src + _i);    \
        }                                                                      \
    } while (0)

    FILL_TAP(0, 0);
    FILL_TAP(TAP_U, 1);
    asm volatile("cp.async.commit_group;");

    // ---- fused attention prologue (overlaps with cp.async flight) ------------
    if (tid < 64) {
        int h = tid >> 3, i = tid & 7;
        float nq = fmaxf(sqrtf(g_sumsq[b * CQK + h * 8 + i]), 1e-12f);
        float temp = temperature[h];
        float row[8];
        float mx = -1e30f;
#pragma unroll
        for (int j = 0; j < 8; j++) {
            float nk = fmaxf(sqrtf(g_sumsq[b * CQK + 64 + h * 8 + j]), 1e-12f);
            float v = g_gram[(b * 8 + h) * 64 + i * 8 + j] / (nq * nk) * temp;
            row[j] = v;
            mx = fmaxf(mx, v);
        }
        float s = 0.0f;
#pragma unroll
        for (int j = 0; j < 8; j++) { row[j] = expf(row[j] - mx); s += row[j]; }
        float inv = 1.0f / s;
#pragma unroll
        for (int j = 0; j < 8; j++) attn_s[tid * 8 + j] = row[j] * inv;
    }

    float acc[2][8][4];
#pragma unroll
    for (int m = 0; m < 2; m++)
#pragma unroll
        for (int n = 0; n < 8; n++)
#pragma unroll
            for (int j = 0; j < 4; j++) acc[m][n][j] = 0.0f;

    // ---- mainloop: 12 full pairs, taps interleaved, ldmatrix B ----------------
    for (int p = 0; p < 12; p++) {
        int slot = ((p + 1) % 3) * PAIR_U;
        FILL_TAP(slot, 2 * p + 2);
        if (2 * p + 3 < 25) FILL_TAP(slot + TAP_U, 2 * p + 3);
        asm volatile("cp.async.commit_group;");
        asm volatile("cp.async.wait_group 1;");
        __syncthreads();

        const uint32_t w0b = ring_base + (uint32_t)((p % 3) * PAIR_U) * 4u + ldsm_lane_off;
        const uint32_t w1b = w0b + (uint32_t)TAP_U * 4u;
        const int t0 = 2 * p, t1 = 2 * p + 1;
        const int dy0 = t0 / 5, dx0 = t0 - 5 * dy0;
        const int dy1 = t1 / 5, dx1 = t1 - 5 * dy1;
        const int roA = (2 * w + dy0) * 20 + dx0 + g;
        const int roB = (2 * w + dy1) * 20 + dx1 + g;

#pragma unroll
        for (int ks = 0; ks < 4; ks++) {
            int ic2a = ks * 8 + t4;
            int ab0 = ic2a * YS2 + roA;
            int ab1 = ic2a * YS2 + roB;
            uint32_t a0[4], a1[4], c0[4], c1[4];
            a0[0] = ysm2[ab0];
            a0[1] = ysm2[ab0 + 8];
            a0[2] = ysm2[ab0 + 4 * YS2];
            a0[3] = ysm2[ab0 + 4 * YS2 + 8];
            a1[0] = ysm2[ab0 + 20];
            a1[1] = ysm2[ab0 + 28];
            a1[2] = ysm2[ab0 + 4 * YS2 + 20];
            a1[3] = ysm2[ab0 + 4 * YS2 + 28];
            c0[0] = ysm2[ab1];
            c0[1] = ysm2[ab1 + 8];
            c0[2] = ysm2[ab1 + 4 * YS2];
            c0[3] = ysm2[ab1 + 4 * YS2 + 8];
            c1[0] = ysm2[ab1 + 20];
            c1[1] = ysm2[ab1 + 28];
            c1[2] = ysm2[ab1 + 4 * YS2 + 20];
            c1[3] = ysm2[ab1 + 4 * YS2 + 28];
#pragma unroll
            for (int np = 0; np < 4; np++) {
                // addr: oc += 16*np rows; k-offset 8*ks uints
                uint32_t off = (uint32_t)((16 * np) * WTR + 8 * ks) * 4u;
                uint32_t B0[4], B1[4];
                ldsm_x4(B0, w0b + off);
                ldsm_x4(B1, w1b + off);
                mma_f16(acc[0][2 * np],     a0, B0);
                mma_f16(acc[1][2 * np],     a1, B0);
                mma_f16(acc[0][2 * np + 1], a0, B0 + 2);
                mma_f16(acc[1][2 * np + 1], a1, B0 + 2);
                mma_f16(acc[0][2 * np],     c0, B1);
                mma_f16(acc[1][2 * np],     c1, B1);
                mma_f16(acc[0][2 * np + 1], c0, B1 + 2);
                mma_f16(acc[1][2 * np + 1], c1, B1 + 2);
            }
        }
    }

    // ---- tail tap 24 (slot 0) --------------------------------------------------
    asm volatile("cp.async.wait_group 0;");
    __syncthreads();
    {
        const uint32_t w0b = ring_base + ldsm_lane_off;   // slot (12 % 3) == 0
        const int ro0 = (2 * w + 4) * 20 + 4 + g;         // dy=4, dx=4
#pragma unroll
        for (int ks = 0; ks < 4; ks++) {
            int ic2a = ks * 8 + t4;
            int abase = ic2a * YS2 + ro0;
            uint32_t a0[4], a1[4];
            a0[0] = ysm2[abase];
            a0[1] = ysm2[abase + 8];
            a0[2] = ysm2[abase + 4 * YS2];
            a0[3] = ysm2[abase + 4 * YS2 + 8];
            a1[0] = ysm2[abase + 20];
            a1[1] = ysm2[abase + 28];
            a1[2] = ysm2[abase + 4 * YS2 + 20];
            a1[3] = ysm2[abase + 4 * YS2 + 28];
#pragma unroll
            for (int np = 0; np < 4; np++) {
                uint32_t off = (uint32_t)((16 * np) * WTR + 8 * ks) * 4u;
                uint32_t B0[4];
                ldsm_x4(B0, w0b + off);
                mma_f16(acc[0][2 * np],     a0, B0);
                mma_f16(acc[1][2 * np],     a1, B0);
                mma_f16(acc[0][2 * np + 1], a0, B0 + 2);
                mma_f16(acc[1][2 * np + 1], a1, B0 + 2);
            }
        }
    }
    __syncthreads();   // mainloop reads done; ysm + ring reusable

    // ---- build M (fp16, into ring space) + gate/stage vv ----------------------
    uint32_t* Msm2 = ring;                  // 32 * 72 (f16x2 [ch2][oc])
    for (int e = tid; e < 2048; e += 256) {
        int oc = e >> 5, ch2 = e & 31;
        int h2 = ch2 >> 2, j0 = (2 * ch2) & 7;
        float s0 = 0.0f, s1 = 0.0f;
#pragma unroll
        for (int i2 = 0; i2 < 8; i2++) {
            float wp = w_proj[oc * 64 + h2 * 8 + i2];
            s0 += wp * attn_s[(h2 * 8 + i2) * 8 + j0];
            s1 += wp * attn_s[(h2 * 8 + i2) * 8 + j0 + 1];
        }
        Msm2[ch2 * WS2 + oc] = packh2(s0, s1);
    }

    uint32_t* vv2 = smu;                    // [ch2][px] f16x2, 32 * 264
#pragma unroll
    for (int m = 0; m < 2; m++) {
        int py = 2 * w + m;
        int gy = ty0 + py;
#pragma unroll
        for (int n = 0; n < 8; n++) {
            float v[4];
#pragma unroll
            for (int j = 0; j < 4; j++) {
                int px = g + ((j >> 1) << 3);
                int ch = n * 8 + t4 * 2 + (j & 1);
                float xv = x[(size_t)(b * 64 + ch) * HW + gy * WDIM + tx0 + px];
                float a = acc[m][n][j];
                float sg = 1.0f / (1.0f + __expf(-a));
                v[j] = xv * (1.0f + sg);
                acc[m][n][j] = 0.0f;
            }
            int ch2 = n * 4 + t4;
            vv2[ch2 * VST2 + py * 16 + g] = packh2(v[0], v[1]);
            vv2[ch2 * VST2 + py * 16 + g + 8] = packh2(v[2], v[3]);
        }
    }
    __syncthreads();

    // ---- epilogue f16 GEMM: out[px][oc] = vv @ M^T ----------------------------
    const int pr0 = 32 * w + g;
#pragma unroll
    for (int ks = 0; ks < 4; ks++) {
        int ch2a = ks * 8 + t4;
        int ab = ch2a * VST2 + pr0;
        uint32_t a0[4], a1[4];
        a0[0] = vv2[ab];
        a0[1] = vv2[ab + 8];
        a0[2] = vv2[ab + 4 * VST2];
        a0[3] = vv2[ab + 4 * VST2 + 8];
        a1[0] = vv2[ab + 16];
        a1[1] = vv2[ab + 24];
        a1[2] = vv2[ab + 4 * VST2 + 16];
        a1[3] = vv2[ab + 4 * VST2 + 24];
        int bbase = ch2a * WS2 + g;
#pragma unroll
        for (int n = 0; n < 8; n++) {
            uint32_t bb[2];
            bb[0] = Msm2[bbase + n * 8];
            bb[1] = Msm2[bbase + 4 * WS2 + n * 8];
            mma_f16(acc[0][n], a0, bb);
            mma_f16(acc[1][n], a1, bb);
        }
    }

#pragma unroll
    for (int m = 0; m < 2; m++) {
        int gy = ty0 + 2 * w + m;
#pragma unroll
        for (int n = 0; n < 8; n++) {
#pragma unroll
            for (int j = 0; j < 4; j++) {
                int px = g + ((j >> 1) << 3);
                int oc = n * 8 + t4 * 2 + (j & 1);
                out[(size_t)(b * 64 + oc) * HW + gy * WDIM + tx0 + px] =
                    acc[m][n][j] + __ldg(&b_proj[oc]);
            }
        }
    }
}

// ---------------- launch ------------------------------------------------------
extern "C" void kernel_launch(void* const* d_in, const int* in_sizes, int n_in,
                              void* d_out, int out_size) {
    const float* x      = (const float*)d_in[0];
    const float* w_qkv  = (const float*)d_in[1];
    const float* b_qkv  = (const float*)d_in[2];
    const float* w_dw   = (const float*)d_in[3];
    const float* b_dw   = (const float*)d_in[4];
    const float* w_proj = (const float*)d_in[5];
    const float* b_proj = (const float*)d_in[6];
    const float* temp   = (const float*)d_in[7];
    const float* w_m1   = (const float*)d_in[8];
    const float* bn_g   = (const float*)d_in[9];
    const float* bn_b   = (const float*)d_in[10];
    const float* bn_m   = (const float*)d_in[11];
    const float* bn_v   = (const float*)d_in[12];
    const float* w_m2   = (const float*)d_in[13];
    float* out = (float*)d_out;

    size_t smem_k0 = (size_t)(32 * XST2 + 32 * WST2 + 384) * sizeof(uint32_t);
    size_t smem_dg = (size_t)TOT_U * sizeof(uint32_t);
    size_t smem_k3 = (size_t)K3_TOT * sizeof(uint32_t);
    cudaFuncSetAttribute(k_pointwise, cudaFuncAttributeMaxDynamicSharedMemorySize,
                         (int)smem_k0);
    cudaFuncSetAttribute(k_dwgram, cudaFuncAttributeMaxDynamicSharedMemorySize,
                         (int)smem_dg);
    cudaFuncSetAttribute(k_conv5_out, cudaFuncAttributeMaxDynamicSharedMemorySize,
                         (int)smem_k3);

    k_prep_pw<<<25, 256>>>(w_qkv, w_m1);
    k_pointwise<<<dim3(HW / 128, B), 256, smem_k0>>>(x, b_qkv, bn_g, bn_b, bn_m,
                                                     bn_v, w_m2);
    k_dwgram<<<dim3(8, 8, B * HEADS), 256, smem_dg>>>(w_dw, b_dw);
    k_conv5_out<<<dim3(16, 16, B), 256, smem_k3>>>(x, w_proj, temp, b_proj, out);
}

// round 13
// speedup vs baseline: 1.0532x; 1.0532x over previous
#include <cuda_runtime.h>
#include <cuda_bf16.h>
#include <cuda_fp16.h>
#include <math.h>
#include <stdint.h>

#define B 4
#define C 64
#define CQK 128
#define HDIM 256
#define WDIM 256
#define HW 65536
#define HEADS 8

// ---------------- scratch ----------------------------------------------------
__device__ __nv_bfloat16 g_qk_pre[(size_t)B * CQK * HW];   // bf16 planar q/k
__device__ uint32_t g_y2[(size_t)B * 32 * HW];             // fp16 ch-pair interleaved
__device__ float g_sumsq[B * CQK];
__device__ float g_gram[B * HEADS * 8 * 8];
__device__ uint32_t g_Wt2[25 * 32 * 64];                   // m2 w: [tap][ic2][oc] f16x2
__device__ uint32_t g_Wpw[32 * 200];                       // qkv+m1 w: [ic2][oc] f16x2

// ---------------- helpers -----------------------------------------------------
__device__ __forceinline__ void mma_f16(float* d, const uint32_t* a, const uint32_t* b) {
    asm volatile(
        "mma.sync.aligned.m16n8k16.row.col.f32.f16.f16.f32 "
        "{%0,%1,%2,%3}, {%4,%5,%6,%7}, {%8,%9}, {%0,%1,%2,%3};"
        : "+f"(d[0]), "+f"(d[1]), "+f"(d[2]), "+f"(d[3])
        : "r"(a[0]), "r"(a[1]), "r"(a[2]), "r"(a[3]), "r"(b[0]), "r"(b[1]));
}

__device__ __forceinline__ void cp_async16(uint32_t daddr, const void* src) {
    asm volatile("cp.async.cg.shared.global [%0], [%1], 16;" :: "r"(daddr), "l"(src));
}

__device__ __forceinline__ void cp_async8(uint32_t daddr, const void* src) {
    asm volatile("cp.async.ca.shared.global [%0], [%1], 8;" :: "r"(daddr), "l"(src));
}

__device__ __forceinline__ void cp_async4_zfill(uint32_t daddr, const void* src, int sz) {
    asm volatile("cp.async.ca.shared.global [%0], [%1], 4, %2;"
                 :: "r"(daddr), "l"(src), "r"(sz));
}

__device__ __forceinline__ float2 bf2f(uint32_t u) {
    float2 r;
    r.x = __uint_as_float(u << 16);
    r.y = __uint_as_float(u & 0xFFFF0000u);
    return r;
}

__device__ __forceinline__ uint32_t packh2(float lo, float hi) {
    __half2 p = __floats2half2_rn(lo, hi);
    return *(uint32_t*)&p;
}

// ---------------- K_prep_pw: pack pointwise weights only ----------------------
__global__ void k_prep_pw(const float* __restrict__ w_qkv,
                          const float* __restrict__ w_m1) {
    int j = blockIdx.x * 256 + threadIdx.x;
    if (j < 6400) {
        int ic2 = j / 200, oc = j - (j / 200) * 200;
        float w0 = 0.0f, w1 = 0.0f;
        if (oc < 128) {
            w0 = w_qkv[oc * 64 + 2 * ic2];
            w1 = w_qkv[oc * 64 + 2 * ic2 + 1];
        } else if (oc < 192) {
            w0 = w_m1[(oc - 128) * 64 + 2 * ic2];
            w1 = w_m1[(oc - 128) * 64 + 2 * ic2 + 1];
        }
        g_Wpw[j] = packh2(w0, w1);
    }
}

// ---------------- K0: fp16-MMA fused 1x1 convs (+ m2 packing + zero) ----------
#define XST2 136
#define WST2 200

__global__ __launch_bounds__(256, 2)
void k_pointwise(const float* __restrict__ x,
                 const float* __restrict__ b_qkv,
                 const float* __restrict__ bn_g,
                 const float* __restrict__ bn_b,
                 const float* __restrict__ bn_m,
                 const float* __restrict__ bn_v,
                 const float* __restrict__ w_m2) {
    extern __shared__ uint32_t smu[];
    uint32_t* xs2 = smu;
    uint32_t* ws2 = smu + 32 * XST2;
    float* sscale = (float*)(smu + 32 * XST2 + 32 * WST2);
    float* sshift = sscale + 192;

    const int tid = threadIdx.x;
    const int b = blockIdx.y;
    const int p0 = blockIdx.x * 128;

    {
        uint32_t base = (uint32_t)__cvta_generic_to_shared(ws2);
        for (int i = tid * 4; i < 6400; i += 1024)
            cp_async16(base + (uint32_t)i * 4u, g_Wpw + i);
        asm volatile("cp.async.commit_group;");
    }

    // ---- side work: pack m2 weights [t][ic2][oc], zero buffers ---------------
    {
        int gbid = blockIdx.y * gridDim.x + blockIdx.x;
        if (gbid < 200) {
            int i = gbid * 256 + tid;        // < 51200
            int t = i / 2048;
            int rem = i & 2047;
            int ic2 = rem >> 6, oc = rem & 63;
            float w0 = w_m2[(oc * 64 + 2 * ic2) * 25 + t];
            float w1 = w_m2[(oc * 64 + 2 * ic2 + 1) * 25 + t];
            g_Wt2[i] = packh2(w0, w1);
        } else if (gbid < 210) {
            int i = (gbid - 200) * 256 + tid;
            if (i < B * CQK) g_sumsq[i] = 0.0f;
            if (i < B * HEADS * 64) g_gram[i] = 0.0f;
        }
    }

    for (int i = tid; i < 192; i += 256) {
        if (i < 128) { sscale[i] = 1.0f; sshift[i] = b_qkv[i]; }
        else {
            int cc = i - 128;
            float s = bn_g[cc] * rsqrtf(bn_v[cc] + 1e-5f);
            sscale[i] = s;
            sshift[i] = bn_b[cc] - bn_m[cc] * s;
        }
    }
    for (int i = tid * 4; i < 32 * 128; i += 1024) {
        int ic2 = i >> 7, px = i & 127;
        float4 xa = *(const float4*)(x + (size_t)(b * 64 + 2 * ic2) * HW + p0 + px);
        float4 xb = *(const float4*)(x + (size_t)(b * 64 + 2 * ic2 + 1) * HW + p0 + px);
        uint4 u;
        u.x = packh2(xa.x, xb.x);
        u.y = packh2(xa.y, xb.y);
        u.z = packh2(xa.z, xb.z);
        u.w = packh2(xa.w, xb.w);
        *(uint4*)(xs2 + ic2 * XST2 + px) = u;
    }
    asm volatile("cp.async.wait_group 0;");
    __syncthreads();

    const int w = tid >> 5, lane = tid & 31;
    const int g = lane >> 2, t4 = lane & 3;
    const int mg = w >> 1, ng = w & 1;
    const int ocb = mg * 48;
    const int pxb = ng * 64;

    float acc[3][8][4];
#pragma unroll
    for (int mt = 0; mt < 3; mt++)
#pragma unroll
        for (int nf = 0; nf < 8; nf++)
#pragma unroll
            for (int j = 0; j < 4; j++) acc[mt][nf][j] = 0.0f;

#pragma unroll
    for (int ks = 0; ks < 4; ks++) {
        int ic2a = ks * 8 + t4;
        uint32_t a[3][4], bf[8][2];
#pragma unroll
        for (int mt = 0; mt < 3; mt++) {
            int ab = ic2a * WST2 + ocb + mt * 16 + g;
            a[mt][0] = ws2[ab];
            a[mt][1] = ws2[ab + 8];
            a[mt][2] = ws2[ab + 4 * WST2];
            a[mt][3] = ws2[ab + 4 * WST2 + 8];
        }
#pragma unroll
        for (int nf = 0; nf < 8; nf++) {
            int bb = ic2a * XST2 + pxb + nf * 8 + g;
            bf[nf][0] = xs2[bb];
            bf[nf][1] = xs2[bb + 4 * XST2];
        }
#pragma unroll
        for (int mt = 0; mt < 3; mt++)
#pragma unroll
            for (int nf = 0; nf < 8; nf++)
                mma_f16(acc[mt][nf], a[mt], bf[nf]);
    }

#pragma unroll
    for (int mt = 0; mt < 3; mt++) {
#pragma unroll
        for (int half = 0; half < 2; half++) {
            int oc = ocb + mt * 16 + half * 8 + g;
            float sc = sscale[oc], sh = sshift[oc];
            bool is_y = (oc >= 128);
#pragma unroll
            for (int nf = 0; nf < 8; nf++) {
                float v0 = acc[mt][nf][half * 2 + 0] * sc + sh;
                float v1 = acc[mt][nf][half * 2 + 1] * sc + sh;
                int px = p0 + pxb + nf * 8 + 2 * t4;
                if (!is_y) {
                    __nv_bfloat162 p = __floats2bfloat162_rn(v0, v1);
                    *(uint32_t*)&g_qk_pre[(size_t)(b * 128 + oc) * HW + px] =
                        *(uint32_t*)&p;
                } else {
                    float o0 = __shfl_down_sync(0xffffffffu, v0, 4);
                    float o1 = __shfl_down_sync(0xffffffffu, v1, 4);
                    if ((g & 1) == 0) {
                        int c2 = (oc - 128) >> 1;
                        uint2 u;
                        u.x = packh2(v0, o0);
                        u.y = packh2(v1, o1);
                        *(uint2*)&g_y2[(size_t)(b * 32 + c2) * HW + px] = u;
                    }
                }
            }
        }
    }
}

// ---------------- K1: depthwise3x3 + mma-Gram + sumsq -------------------------
#define SR_U 18
#define CH_U 616
#define DV_OFF (16 * CH_U)
#define DV_CH 516
#define WSM_U (DV_OFF + 16 * DV_CH)
#define BSM_U (WSM_U + 144)
#define TOT_U (BSM_U + 16)

__global__ __launch_bounds__(256, 3)
void k_dwgram(const float* __restrict__ w_dw,
              const float* __restrict__ b_dw) {
    extern __shared__ uint32_t smu[];
    float* wsm = (float*)(smu + WSM_U);
    float* bsm = (float*)(smu + BSM_U);

    const int bh = blockIdx.z;
    const int b = bh >> 3, h = bh & 7;
    const int tx0 = blockIdx.x * 32, ty0 = blockIdx.y * 32;
    const int tid = threadIdx.x;
    const int w = tid >> 5, lane = tid & 31;
    const int g = lane >> 2, t4 = lane & 3;
    const uint32_t smbase = (uint32_t)__cvta_generic_to_shared(smu);

    // ---- stage input halo via cp.async 4B (zfill for OOB) ---------------------
    const __nv_bfloat16* gbase = g_qk_pre + (size_t)b * CQK * HW;
#pragma unroll
    for (int k = 0; k < 39; k++) {
        int idx = tid + k * 256;
        if (idx < 16 * 34 * SR_U) {
            int c16 = idx / (34 * SR_U);
            int rem = idx - c16 * (34 * SR_U);
            int r = rem / SR_U, cc = rem - r * SR_U;
            int ch = (c16 < 8) ? h * 8 + c16 : 64 + h * 8 + (c16 - 8);
            int gy = ty0 - 1 + r;
            int gx = tx0 - 2 + 2 * cc;
            bool ok = (gy >= 0) && (gy < HDIM) && (gx >= 0) && (gx < WDIM);
            const void* src = ok ? (const void*)(gbase + (size_t)ch * HW + gy * WDIM + gx)
                                 : (const void*)gbase;
            cp_async4_zfill(smbase + (uint32_t)(c16 * CH_U + r * SR_U + cc) * 4u,
                            src, ok ? 4 : 0);
        }
    }
    asm volatile("cp.async.commit_group;");

    for (int i = tid; i < 144; i += 256) {
        int c16 = i / 9, t = i - c16 * 9;
        int ch = (c16 < 8) ? h * 8 + c16 : 64 + h * 8 + (c16 - 8);
        wsm[i] = w_dw[ch * 9 + t];
    }
    if (tid < 16) {
        int ch = (tid < 8) ? h * 8 + tid : 64 + h * 8 + (tid - 8);
        bsm[tid] = b_dw[ch];
    }
    asm volatile("cp.async.wait_group 0;");
    __syncthreads();

    // ---- phase A: depthwise for own 4-px strip, dv -> smem (fp16) -------------
    const int q = tid & 7, py = tid >> 3;
#pragma unroll
    for (int c16 = 0; c16 < 16; c16++) {
        float f[3][8];
#pragma unroll
        for (int dy = 0; dy < 3; dy++) {
            const uint2* p2 = (const uint2*)(smu + c16 * CH_U + (py + dy) * SR_U + 2 * q);
            uint2 u01 = p2[0], u23 = p2[1];
            float2 a0 = bf2f(u01.x), a1 = bf2f(u01.y);
            float2 a2 = bf2f(u23.x), a3 = bf2f(u23.y);
            f[dy][0] = a0.x; f[dy][1] = a0.y; f[dy][2] = a1.x; f[dy][3] = a1.y;
            f[dy][4] = a2.x; f[dy][5] = a2.y; f[dy][6] = a3.x; f[dy][7] = a3.y;
        }
        float bias = bsm[c16];
        float o[4];
#pragma unroll
        for (int xx = 0; xx < 4; xx++) {
            float a = bias;
#pragma unroll
            for (int dy = 0; dy < 3; dy++) {
                a = fmaf(wsm[c16 * 9 + dy * 3 + 0], f[dy][xx + 1], a);
                a = fmaf(wsm[c16 * 9 + dy * 3 + 1], f[dy][xx + 2], a);
                a = fmaf(wsm[c16 * 9 + dy * 3 + 2], f[dy][xx + 3], a);
            }
            o[xx] = a;
        }
        uint2 dvu;
        dvu.x = packh2(o[0], o[1]);
        dvu.y = packh2(o[2], o[3]);
        *(uint2*)(smu + DV_OFF + c16 * DV_CH + py * 16 + 2 * q) = dvu;
    }
    __syncthreads();

    // ---- zero 16x17 gram tile in smem (input region is free now) -------------
    float* gram16 = (float*)smu;
    for (int i = tid; i < 16 * 17; i += 256) gram16[i] = 0.0f;
    __syncthreads();

    // ---- phase B: warp-local 16x16 Gram via fp16 mma (B frags == A frags) -----
    float gc0[4] = {0.f, 0.f, 0.f, 0.f};
    float gc1[4] = {0.f, 0.f, 0.f, 0.f};
    const uint32_t* dvu = smu + DV_OFF;
    const int sbase = w * 64;                 // warp w: px-uints [64w, 64w+64)
#pragma unroll
    for (int s = 0; s < 8; s++) {
        int base = sbase + s * 8 + t4;
        uint32_t A[4];
        A[0] = dvu[g * DV_CH + base];
        A[1] = dvu[(g + 8) * DV_CH + base];
        A[2] = dvu[g * DV_CH + base + 4];
        A[3] = dvu[(g + 8) * DV_CH + base + 4];
        uint32_t B0[2] = {A[0], A[2]};        // N = ch 0..7
        uint32_t B1[2] = {A[1], A[3]};        // N = ch 8..15
        mma_f16(gc0, A, B0);
        mma_f16(gc1, A, B1);
    }

    // ---- accumulate into smem gram tile ---------------------------------------
    atomicAdd(&gram16[g * 17 + 2 * t4],            gc0[0]);
    atomicAdd(&gram16[g * 17 + 2 * t4 + 1],        gc0[1]);
    atomicAdd(&gram16[(g + 8) * 17 + 2 * t4],      gc0[2]);
    atomicAdd(&gram16[(g + 8) * 17 + 2 * t4 + 1],  gc0[3]);
    atomicAdd(&gram16[g * 17 + 8 + 2 * t4],        gc1[0]);
    atomicAdd(&gram16[g * 17 + 8 + 2 * t4 + 1],    gc1[1]);
    atomicAdd(&gram16[(g + 8) * 17 + 8 + 2 * t4],  gc1[2]);
    atomicAdd(&gram16[(g + 8) * 17 + 8 + 2 * t4 + 1], gc1[3]);
    __syncthreads();

    // ---- export: gram = rows 0..7 x cols 8..15; ssq = diagonal ----------------
    if (tid < 64) {
        int i = tid >> 3, j = tid & 7;
        atomicAdd(&g_gram[bh * 64 + i * 8 + j], gram16[i * 17 + 8 + j]);
    } else if (tid < 80) {
        int c16 = tid - 64;
        int ch = (c16 < 8) ? h * 8 + c16 : 64 + h * 8 + (c16 - 8);
        atomicAdd(&g_sumsq[b * CQK + ch], gram16[c16 * 17 + c16]);
    }
}

// ---------------- K3: fp16 conv5x5 (R11 winner) + gate + fp16 epilogue --------
#define YS2 408
#define WS2 72
#define VST2 264
#define RING_OFF (32 * YS2)
#define TAP_U (32 * WS2)
#define PAIR_U (2 * TAP_U)
#define ATTN_OFF (RING_OFF + 3 * PAIR_U)
#define K3_TOT (ATTN_OFF + 512)

__global__ __launch_bounds__(256, 2)
void k_conv5_out(const float* __restrict__ x,
                 const float* __restrict__ w_proj,
                 const float* __restrict__ temperature,
                 const float* __restrict__ b_proj,
                 float* __restrict__ out) {
    extern __shared__ uint32_t smu[];
    uint32_t* ysm2 = smu;
    uint32_t* ring = smu + RING_OFF;
    float* attn_s  = (float*)(smu + ATTN_OFF);

    const int b = blockIdx.z;
    const int tx0 = blockIdx.x * 16, ty0 = blockIdx.y * 16;
    const int tid = threadIdx.x;
    const int w = tid >> 5, lane = tid & 31;
    const int g = lane >> 2, t4 = lane & 3;
    const uint32_t smbase = (uint32_t)__cvta_generic_to_shared(smu);

    const bool interior = (blockIdx.x >= 1) && (blockIdx.x <= 14) &&
                          (blockIdx.y >= 1) && (blockIdx.y <= 14);
    if (interior) {
        const uint32_t* yb = g_y2 + (size_t)(b * 32) * HW + (ty0 - 2) * WDIM + (tx0 - 2);
#pragma unroll
        for (int k = 0; k < 25; k++) {
            int i = tid + k * 256;
            int ic2 = i / 200;
            int rem = i - ic2 * 200;
            int r = rem / 10, cc = rem - r * 10;
            cp_async8(smbase + (uint32_t)((ic2 * YS2 + r * 20 + cc * 2) * 4),
                      yb + (size_t)ic2 * HW + r * WDIM + cc * 2);
        }
    } else {
        for (int i = tid; i < 32 * 400; i += 256) {
            int ic2 = i / 400;
            int rem = i - ic2 * 400;
            int r = rem / 20, cc = rem - r * 20;
            int gy = ty0 - 2 + r, gx = tx0 - 2 + cc;
            uint32_t v = 0;
            if (gy >= 0 && gy < HDIM && gx >= 0 && gx < WDIM)
                v = g_y2[(size_t)(b * 32 + ic2) * HW + gy * WDIM + gx];
            ysm2[ic2 * YS2 + r * 20 + cc] = v;
        }
    }
#define FILL_TAP(slot_u, tap)                                                  \
    do {                                                                       \
        const uint32_t* _src = g_Wt2 + (tap) * 2048;                           \
        uint32_t _db = smbase + (uint32_t)((RING_OFF + (slot_u)) * 4);         \
        for (int _i = tid * 4; _i < 2048; _i += 1024) {                        \
            int _ic2 = _i >> 6, _oc = _i & 63;                                 \
            cp_async16(_db + (uint32_t)(_ic2 * WS2 + _oc) * 4u, _src + _i);    \
        }                                                                      \
    } while (0)

    FILL_TAP(0, 0);
    FILL_TAP(TAP_U, 1);
    asm volatile("cp.async.commit_group;");

    // ---- fused attention prologue ---------------------------------------------
    if (tid < 64) {
        int h = tid >> 3, i = tid & 7;
        float nq = fmaxf(sqrtf(g_sumsq[b * CQK + h * 8 + i]), 1e-12f);
        float temp = temperature[h];
        float row[8];
        float mx = -1e30f;
#pragma unroll
        for (int j = 0; j < 8; j++) {
            float nk = fmaxf(sqrtf(g_sumsq[b * CQK + 64 + h * 8 + j]), 1e-12f);
            float v = g_gram[(b * 8 + h) * 64 + i * 8 + j] / (nq * nk) * temp;
            row[j] = v;
            mx = fmaxf(mx, v);
        }
        float s = 0.0f;
#pragma unroll
        for (int j = 0; j < 8; j++) { row[j] = expf(row[j] - mx); s += row[j]; }
        float inv = 1.0f / s;
#pragma unroll
        for (int j = 0; j < 8; j++) attn_s[tid * 8 + j] = row[j] * inv;
    }

    float acc[2][8][4];
#pragma unroll
    for (int m = 0; m < 2; m++)
#pragma unroll
        for (int n = 0; n < 8; n++)
#pragma unroll
            for (int j = 0; j < 4; j++) acc[m][n][j] = 0.0f;

    // ---- mainloop: 12 full pairs, taps interleaved -----------------------------
    for (int p = 0; p < 12; p++) {
        int slot = ((p + 1) % 3) * PAIR_U;
        FILL_TAP(slot, 2 * p + 2);
        if (2 * p + 3 < 25) FILL_TAP(slot + TAP_U, 2 * p + 3);
        asm volatile("cp.async.commit_group;");
        asm volatile("cp.async.wait_group 1;");
        __syncthreads();

        const uint32_t* w0 = ring + (p % 3) * PAIR_U;
        const uint32_t* w1 = w0 + TAP_U;
        const int t0 = 2 * p, t1 = 2 * p + 1;
        const int dy0 = t0 / 5, dx0 = t0 - 5 * dy0;
        const int dy1 = t1 / 5, dx1 = t1 - 5 * dy1;
        const int roA = (2 * w + dy0) * 20 + dx0 + g;
        const int roB = (2 * w + dy1) * 20 + dx1 + g;

#pragma unroll
        for (int ks = 0; ks < 4; ks++) {
            int ic2a = ks * 8 + t4;
            int ab0 = ic2a * YS2 + roA;
            int ab1 = ic2a * YS2 + roB;
            uint32_t a0[4], a1[4], c0[4], c1[4];
            a0[0] = ysm2[ab0];
            a0[1] = ysm2[ab0 + 8];
            a0[2] = ysm2[ab0 + 4 * YS2];
            a0[3] = ysm2[ab0 + 4 * YS2 + 8];
            a1[0] = ysm2[ab0 + 20];
            a1[1] = ysm2[ab0 + 28];
            a1[2] = ysm2[ab0 + 4 * YS2 + 20];
            a1[3] = ysm2[ab0 + 4 * YS2 + 28];
            c0[0] = ysm2[ab1];
            c0[1] = ysm2[ab1 + 8];
            c0[2] = ysm2[ab1 + 4 * YS2];
            c0[3] = ysm2[ab1 + 4 * YS2 + 8];
            c1[0] = ysm2[ab1 + 20];
            c1[1] = ysm2[ab1 + 28];
            c1[2] = ysm2[ab1 + 4 * YS2 + 20];
            c1[3] = ysm2[ab1 + 4 * YS2 + 28];
            int bbase = ic2a * WS2 + g;
#pragma unroll
            for (int n = 0; n < 8; n++) {
                uint32_t b0[2], b1[2];
                b0[0] = w0[bbase + n * 8];
                b0[1] = w0[bbase + 4 * WS2 + n * 8];
                b1[0] = w1[bbase + n * 8];
                b1[1] = w1[bbase + 4 * WS2 + n * 8];
                mma_f16(acc[0][n], a0, b0);
                mma_f16(acc[1][n], a1, b0);
                mma_f16(acc[0][n], c0, b1);
                mma_f16(acc[1][n], c1, b1);
            }
        }
    }

    // ---- tail tap 24 (slot 0) --------------------------------------------------
    asm volatile("cp.async.wait_group 0;");
    __syncthreads();
    {
        const uint32_t* w0 = ring;
        const int ro0 = (2 * w + 4) * 20 + 4 + g;
#pragma unroll
        for (int ks = 0; ks < 4; ks++) {
            int ic2a = ks * 8 + t4;
            int abase = ic2a * YS2 + ro0;
            uint32_t a0[4], a1[4];
            a0[0] = ysm2[abase];
            a0[1] = ysm2[abase + 8];
            a0[2] = ysm2[abase + 4 * YS2];
            a0[3] = ysm2[abase + 4 * YS2 + 8];
            a1[0] = ysm2[abase + 20];
            a1[1] = ysm2[abase + 28];
            a1[2] = ysm2[abase + 4 * YS2 + 20];
            a1[3] = ysm2[abase + 4 * YS2 + 28];
            int bbase = ic2a * WS2 + g;
#pragma unroll
            for (int n = 0; n < 8; n++) {
                uint32_t bb[2];
                bb[0] = w0[bbase + n * 8];
                bb[1] = w0[bbase + 4 * WS2 + n * 8];
                mma_f16(acc[0][n], a0, bb);
                mma_f16(acc[1][n], a1, bb);
            }
        }
    }
    __syncthreads();

    // ---- build M (fp16, into ring space) + gate/stage vv ----------------------
    uint32_t* Msm2 = ring;
    for (int e = tid; e < 2048; e += 256) {
        int oc = e >> 5, ch2 = e & 31;
        int h2 = ch2 >> 2, j0 = (2 * ch2) & 7;
        float s0 = 0.0f, s1 = 0.0f;
#pragma unroll
        for (int i2 = 0; i2 < 8; i2++) {
            float wp = w_proj[oc * 64 + h2 * 8 + i2];
            s0 += wp * attn_s[(h2 * 8 + i2) * 8 + j0];
            s1 += wp * attn_s[(h2 * 8 + i2) * 8 + j0 + 1];
        }
        Msm2[ch2 * WS2 + oc] = packh2(s0, s1);
    }

    uint32_t* vv2 = smu;
#pragma unroll
    for (int m = 0; m < 2; m++) {
        int py = 2 * w + m;
        int gy = ty0 + py;
#pragma unroll
        for (int n = 0; n < 8; n++) {
            float v[4];
#pragma unroll
            for (int j = 0; j < 4; j++) {
                int px = g + ((j >> 1) << 3);
                int ch = n * 8 + t4 * 2 + (j & 1);
                float xv = x[(size_t)(b * 64 + ch) * HW + gy * WDIM + tx0 + px];
                float a = acc[m][n][j];
                float sg = 1.0f / (1.0f + __expf(-a));
                v[j] = xv * (1.0f + sg);
                acc[m][n][j] = 0.0f;
            }
            int ch2 = n * 4 + t4;
            vv2[ch2 * VST2 + py * 16 + g] = packh2(v[0], v[1]);
            vv2[ch2 * VST2 + py * 16 + g + 8] = packh2(v[2], v[3]);
        }
    }
    __syncthreads();

    // ---- epilogue f16 GEMM -----------------------------------------------------
    const int pr0 = 32 * w + g;
#pragma unroll
    for (int ks = 0; ks < 4; ks++) {
        int ch2a = ks * 8 + t4;
        int ab = ch2a * VST2 + pr0;
        uint32_t a0[4], a1[4];
        a0[0] = vv2[ab];
        a0[1] = vv2[ab + 8];
        a0[2] = vv2[ab + 4 * VST2];
        a0[3] = vv2[ab + 4 * VST2 + 8];
        a1[0] = vv2[ab + 16];
        a1[1] = vv2[ab + 24];
        a1[2] = vv2[ab + 4 * VST2 + 16];
        a1[3] = vv2[ab + 4 * VST2 + 24];
        int bbase = ch2a * WS2 + g;
#pragma unroll
        for (int n = 0; n < 8; n++) {
            uint32_t bb[2];
            bb[0] = Msm2[bbase + n * 8];
            bb[1] = Msm2[bbase + 4 * WS2 + n * 8];
            mma_f16(acc[0][n], a0, bb);
            mma_f16(acc[1][n], a1, bb);
        }
    }

#pragma unroll
    for (int m = 0; m < 2; m++) {
        int gy = ty0 + 2 * w + m;
#pragma unroll
        for (int n = 0; n < 8; n++) {
#pragma unroll
            for (int j = 0; j < 4; j++) {
                int px = g + ((j >> 1) << 3);
                int oc = n * 8 + t4 * 2 + (j & 1);
                out[(size_t)(b * 64 + oc) * HW + gy * WDIM + tx0 + px] =
                    acc[m][n][j] + __ldg(&b_proj[oc]);
            }
        }
    }
}

// ---------------- launch ------------------------------------------------------
extern "C" void kernel_launch(void* const* d_in, const int* in_sizes, int n_in,
                              void* d_out, int out_size) {
    const float* x      = (const float*)d_in[0];
    const float* w_qkv  = (const float*)d_in[1];
    const float* b_qkv  = (const float*)d_in[2];
    const float* w_dw   = (const float*)d_in[3];
    const float* b_dw   = (const float*)d_in[4];
    const float* w_proj = (const float*)d_in[5];
    const float* b_proj = (const float*)d_in[6];
    const float* temp   = (const float*)d_in[7];
    const float* w_m1   = (const float*)d_in[8];
    const float* bn_g   = (const float*)d_in[9];
    const float* bn_b   = (const float*)d_in[10];
    const float* bn_m   = (const float*)d_in[11];
    const float* bn_v   = (const float*)d_in[12];
    const float* w_m2   = (const float*)d_in[13];
    float* out = (float*)d_out;

    size_t smem_k0 = (size_t)(32 * XST2 + 32 * WST2 + 384) * sizeof(uint32_t);
    size_t smem_dg = (size_t)TOT_U * sizeof(uint32_t);
    size_t smem_k3 = (size_t)K3_TOT * sizeof(uint32_t);
    cudaFuncSetAttribute(k_pointwise, cudaFuncAttributeMaxDynamicSharedMemorySize,
                         (int)smem_k0);
    cudaFuncSetAttribute(k_dwgram, cudaFuncAttributeMaxDynamicSharedMemorySize,
                         (int)smem_dg);
    cudaFuncSetAttribute(k_conv5_out, cudaFuncAttributeMaxDynamicSharedMemorySize,
                         (int)smem_k3);

    k_prep_pw<<<25, 256>>>(w_qkv, w_m1);
    k_pointwise<<<dim3(HW / 128, B), 256, smem_k0>>>(x, b_qkv, bn_g, bn_b, bn_m,
                                                     bn_v, w_m2);
    k_dwgram<<<dim3(8, 8, B * HEADS), 256, smem_dg>>>(w_dw, b_dw);
    k_conv5_out<<<dim3(16, 16, B), 256, smem_k3>>>(x, w_proj, temp, b_proj, out);
}